// round 7
// baseline (speedup 1.0000x reference)
#include <cuda_runtime.h>
#include <cstdint>

// ---------------- problem constants ----------------
#define HH   48
#define WW   160
#define BB   32
#define CIn  32
#define NG   160            // 5*CL
#define CO_  64
#define HOo  24
#define WOo  80
#define CELLSZ 1024         // B*CL
#define DIRSZ  (HH*WW*CELLSZ)
#define NPAIR 24            // HH/2

// ---------------- device scratch (static: allocation-free) ----------------
__device__ float    g_xT[HH*WW*BB*CIn];      // [r][c][b][ci]
__device__ float    g_hd[4*DIRSZ];           // h per direction, scan coords
__device__ float    g_cd[4*DIRSZ];           // c per direction (odd rows used)
__device__ unsigned g_prog[4*NPAIR];         // per-(dir,pair) boundary progress
__device__ float    g_y [BB*CO_*HOo*WOo];    // pre-norm conv output
__device__ float    g_ps1[BB*HOo*CO_];
__device__ float    g_ps2[BB*HOo*CO_];
__device__ float    g_sc[CO_];
__device__ float    g_sh[CO_];

// ---------------- helpers ----------------
__device__ __forceinline__ unsigned ld_acq(const unsigned* p) {
    unsigned v;
    asm volatile("ld.acquire.gpu.global.u32 %0, [%1];" : "=r"(v) : "l"(p) : "memory");
    return v;
}
__device__ __forceinline__ void st_rel(unsigned* p, unsigned v) {
    asm volatile("st.release.gpu.global.u32 [%0], %1;" :: "l"(p), "r"(v) : "memory");
}
__device__ __forceinline__ float fsigmoid(float x) {
    float e = __expf(-x);
    return __fdividef(1.0f, 1.0f + e);
}
__device__ __forceinline__ float ftanh(float x) {
    float ax = fabsf(x);
    float e  = __expf(-2.0f * ax);          // in (0,1], never overflows
    float r  = __fdividef(1.0f - e, 1.0f + e);
    return copysignf(r, x);
}

// ---------------- kernel 0: transpose x + reset progress ----------------
__global__ void prep_kernel(const float* __restrict__ x) {
    int t = blockIdx.x * blockDim.x + threadIdx.x;   // 7680*256 threads, 1 float4 each
    if (t < 4*NPAIR) g_prog[t] = 0;
    int i0 = t * 4;
    int ci = i0 & 31;
    int b  = (i0 >> 5) & 31;
    int c  = (i0 >> 10) % WW;
    int r  = i0 / (WW * CELLSZ);
    const float* xp = x + (((size_t)(b*CIn + ci))*HH + r)*WW + c;
    float4 v;
    v.x = xp[0];
    v.y = xp[(size_t)HH*WW];
    v.z = xp[2*(size_t)HH*WW];
    v.w = xp[3*(size_t)HH*WW];
    *(float4*)(g_xT + i0) = v;
}

// ---------------- kernel 1: 4-dir MDLSTM, paired rows, 96 CTAs x 512 thr ----------------
#define AP 100
#define ZP 164
#define SM_WS  0
#define SM_BS  15360
#define SM_AS  15520
#define SM_ZS  21920
#define SM_CL  32416
#define SM_CT0 34464
#define SM_CT1 35488
#define SM_PS  36512
#define SM_TOT 46752     // floats -> 187,008 bytes

__launch_bounds__(512, 1)
__global__ void mdlstm_kernel(const float* __restrict__ Wx, const float* __restrict__ Ul,
                              const float* __restrict__ Ut, const float* __restrict__ bias) {
    extern __shared__ float sm[];
    float* Ws  = sm + SM_WS;    // [96][160]: k 0..31 Wx, 32..63 Ul, 64..95 Ut
    float* Bs  = sm + SM_BS;
    float* As  = sm + SM_AS;    // [64][100]: rows 0..31 cell0, 32..63 cell1
    float* Zs  = sm + SM_ZS;    // [64][164]
    float* Cl  = sm + SM_CL;    // c_left [64*32]
    float* Ct0 = sm + SM_CT0;   // c_top for cell0 (external)
    float* Ct1 = sm + SM_CT1;   // c_top for cell1 (= c(r0, prev col))
    unsigned long long* Ps = (unsigned long long*)(sm + SM_PS);  // [20][256] u64 partials

    const int tid = threadIdx.x;
    const int d   = blockIdx.x / NPAIR;
    const int p   = blockIdx.x % NPAIR;
    const bool flipH = (d >= 2);
    const bool flipW = (d & 1);
    const int r0  = 2*p;
    const int r1  = 2*p + 1;
    const int r0o = flipH ? (HH-1-r0) : r0;
    const int r1o = flipH ? (HH-1-r1) : r1;

    for (int i = tid; i < 32*NG; i += 512) {
        Ws[i]         = Wx[d*32*NG + i];
        Ws[32*NG + i] = Ul[d*32*NG + i];
        Ws[64*NG + i] = Ut[d*32*NG + i];
    }
    if (tid < NG) Bs[tid] = bias[d*NG + tid];
    for (int i = tid; i < 2048; i += 512) {
        int row = i >> 5, cl = i & 31;
        As[row*AP + 32 + cl] = 0.0f;
        As[row*AP + 64 + cl] = 0.0f;
        Cl[i] = 0.0f;
        if (i < 1024) { Ct0[i] = 0.0f; Ct1[i] = 0.0f; }
    }
    __syncthreads();

    const int kh  = tid >> 8;            // split-k half
    const int t8  = tid & 255;
    const int rg  = t8 >> 3;             // row-pair index (0..31)
    const int cg  = t8 & 7;              // 20 contiguous output cols
    const int gcl = tid & 31;            // gates: cell channel
    const int gb0 = (tid >> 5) * 4;      // gates: 4 A-rows each
    unsigned* myflag = &g_prog[d*NPAIR + p];
    const unsigned* upflag = (p > 0) ? &g_prog[d*NPAIR + p - 1] : 0;

    for (int t = 0; t <= WW; ++t) {
        // ---- staging: x LDGs first (latency hides under the spin) ----
        float4 xv;
        bool xact = (tid < 256) ? (t < WW) : (t >= 1);
        if (xact) {
            if (tid < 256) {
                int c = flipW ? (WW-1-t) : t;
                xv = *(const float4*)(g_xT + ((size_t)(r0o*WW + c))*CELLSZ + tid*4);
            } else {
                int c1 = t - 1;
                int c  = flipW ? (WW-1-c1) : c1;
                xv = *(const float4*)(g_xT + ((size_t)(r1o*WW + c))*CELLSZ + (tid-256)*4);
            }
        }
        if (t < WW && p > 0) {
            if (tid == 0) { while ((int)ld_acq(upflag) < t + 1) { } }
            __syncthreads();
            size_t hb = (((size_t)(d*HH + r0 - 1))*WW + t)*CELLSZ;
            if (tid < 256) {
                float4 hv = *(const float4*)(g_hd + hb + tid*4);
                *(float4*)(As + (tid>>3)*AP + 64 + ((tid&7)*4)) = hv;
            } else {
                float4 cv = *(const float4*)(g_cd + hb + (tid-256)*4);
                *(float4*)(Ct0 + (tid-256)*4) = cv;
            }
        }
        if (xact) {
            if (tid < 256) *(float4*)(As + (tid>>3)*AP + ((tid&7)*4)) = xv;
            else           *(float4*)(As + (32 + ((tid-256)>>3))*AP + (((tid-256)&7)*4)) = xv;
        }
        __syncthreads();

        // ---- split-k GEMM: Z[64][160] = A[64][96] @ W[96][160] + bias ----
        {
            unsigned long long acc0[10], acc1[10];
            if (kh == 0) {
                const ulonglong2* bp = (const ulonglong2*)(Bs + cg*20);
                #pragma unroll
                for (int j = 0; j < 5; ++j) {
                    ulonglong2 bv = bp[j];
                    acc0[2*j] = bv.x; acc0[2*j+1] = bv.y;
                    acc1[2*j] = bv.x; acc1[2*j+1] = bv.y;
                }
            } else {
                #pragma unroll
                for (int j = 0; j < 10; ++j) { acc0[j] = 0ull; acc1[j] = 0ull; }
            }
            const float* arow0 = As + (2*rg)*AP + kh*48;
            const float* arow1 = arow0 + AP;
            const float* wcol  = Ws + (kh*48)*NG + cg*20;
            #pragma unroll 2
            for (int k0 = 0; k0 < 48; k0 += 8) {
                float4 a0lo = *(const float4*)(arow0 + k0);
                float4 a0hi = *(const float4*)(arow0 + k0 + 4);
                float4 a1lo = *(const float4*)(arow1 + k0);
                float4 a1hi = *(const float4*)(arow1 + k0 + 4);
                float a0s[8] = {a0lo.x, a0lo.y, a0lo.z, a0lo.w, a0hi.x, a0hi.y, a0hi.z, a0hi.w};
                float a1s[8] = {a1lo.x, a1lo.y, a1lo.z, a1lo.w, a1hi.x, a1hi.y, a1hi.z, a1hi.w};
                #pragma unroll
                for (int kk = 0; kk < 8; ++kk) {
                    unsigned long long aa0, aa1;
                    asm("mov.b64 %0, {%1, %1};" : "=l"(aa0) : "f"(a0s[kk]));
                    asm("mov.b64 %0, {%1, %1};" : "=l"(aa1) : "f"(a1s[kk]));
                    const ulonglong2* wp = (const ulonglong2*)(wcol + (k0 + kk)*NG);
                    #pragma unroll
                    for (int j = 0; j < 5; ++j) {
                        ulonglong2 wv = wp[j];
                        asm("fma.rn.f32x2 %0, %1, %2, %0;" : "+l"(acc0[2*j])   : "l"(wv.x), "l"(aa0));
                        asm("fma.rn.f32x2 %0, %1, %2, %0;" : "+l"(acc0[2*j+1]) : "l"(wv.y), "l"(aa0));
                        asm("fma.rn.f32x2 %0, %1, %2, %0;" : "+l"(acc1[2*j])   : "l"(wv.x), "l"(aa1));
                        asm("fma.rn.f32x2 %0, %1, %2, %0;" : "+l"(acc1[2*j+1]) : "l"(wv.y), "l"(aa1));
                    }
                }
            }
            if (kh == 1) {
                #pragma unroll
                for (int j = 0; j < 10; ++j) Ps[j*256 + t8] = acc0[j];
                #pragma unroll
                for (int j = 0; j < 10; ++j) Ps[(10+j)*256 + t8] = acc1[j];
            }
            __syncthreads();
            if (kh == 0) {
                #pragma unroll
                for (int j = 0; j < 10; ++j) {
                    unsigned long long v = Ps[j*256 + t8];
                    asm("add.rn.f32x2 %0, %0, %1;" : "+l"(acc0[j]) : "l"(v));
                }
                #pragma unroll
                for (int j = 0; j < 10; ++j) {
                    unsigned long long v = Ps[(10+j)*256 + t8];
                    asm("add.rn.f32x2 %0, %0, %1;" : "+l"(acc1[j]) : "l"(v));
                }
                ulonglong2* zp0 = (ulonglong2*)(Zs + (2*rg)*ZP + cg*20);
                ulonglong2* zp1 = (ulonglong2*)(Zs + (2*rg+1)*ZP + cg*20);
                #pragma unroll
                for (int j = 0; j < 5; ++j) {
                    ulonglong2 v0; v0.x = acc0[2*j]; v0.y = acc0[2*j+1]; zp0[j] = v0;
                    ulonglong2 v1; v1.x = acc1[2*j]; v1.y = acc1[2*j+1]; zp1[j] = v1;
                }
            }
        }
        __syncthreads();

        // ---- gates for both cells (4 rows per thread) ----
        {
            const bool act0 = (t < WW);
            const bool act1 = (t >= 1);
            size_t base0 = (((size_t)(d*HH + r0))*WW + t)*CELLSZ;
            size_t base1 = (((size_t)(d*HH + r1))*WW + (t-1))*CELLSZ;
            #pragma unroll
            for (int j = 0; j < 4; ++j) {
                int gr = gb0 + j;
                const float* z = Zs + gr*ZP + gcl;
                float zi  = z[0];
                float zfl = z[32];
                float zft = z[64];
                float zo  = z[96];
                float zg  = z[128];
                int b = gr & 31;
                float cle = Cl[gr*32 + gcl];
                float cto = (gr < 32) ? Ct0[b*32 + gcl] : Ct1[b*32 + gcl];
                float cs = fsigmoid(zfl)*cle + fsigmoid(zft)*cto
                         + fsigmoid(zi)*ftanh(zg);
                float h  = fsigmoid(zo)*ftanh(cs);
                if (gr < 32) {
                    if (act0) {
                        Cl[gr*32 + gcl]          = cs;
                        As[gr*AP + 32 + gcl]     = h;     // h_left(r0)
                        Ct1[b*32 + gcl]          = cs;    // c_top for cell1 next step
                        As[(32+b)*AP + 64 + gcl] = h;     // h_top for cell1 next step
                        g_hd[base0 + b*32 + gcl] = h;
                    }
                } else {
                    if (act1) {
                        Cl[gr*32 + gcl]          = cs;
                        As[gr*AP + 32 + gcl]     = h;     // h_left(r1)
                        g_hd[base1 + b*32 + gcl] = h;     // boundary row
                        g_cd[base1 + b*32 + gcl] = cs;
                    }
                }
            }
        }
        __syncthreads();
        if (tid == 0 && t >= 1) {
            __threadfence();
            st_rel(myflag, (unsigned)t);
        }
    }
}

// ---------------- kernel 2: 4-dir sum + 2x2/2 conv + tanh + partial stats ----------------
__launch_bounds__(256, 2)
__global__ void conv_kernel(const float* __restrict__ conv_w, const float* __restrict__ conv_b) {
    extern __shared__ float sm2[];
    float* Hs = sm2;            // [rr][c][cl]  2*160*32
    float* Wt = sm2 + 10240;    // [cl*4+kh*2+kw][co] 128*64
    const int ho  = blockIdx.x;
    const int b   = blockIdx.y;
    const int tid = threadIdx.x;

    for (int i = tid; i < 128*64; i += 256) {
        int co = i & 63, q = i >> 6;
        Wt[i] = conv_w[co*128 + q];
    }
    for (int idx = tid; idx < 2*WW*32; idx += 256) {
        int cl = idx & 31;
        int c  = (idx >> 5) % WW;
        int rr = idx / (WW*32);
        int rg = 2*ho + rr;
        float v = 0.0f;
        #pragma unroll
        for (int d = 0; d < 4; ++d) {
            int Rd = (d >= 2) ? (HH-1-rg) : rg;
            int Cd = (d & 1)  ? (WW-1-c)  : c;
            v += g_hd[(((size_t)(d*HH + Rd))*WW + Cd)*CELLSZ + b*32 + cl];
        }
        Hs[idx] = v;
    }
    __syncthreads();

    const int co = tid >> 2;
    const int ws = tid & 3;
    float acc[20];
    #pragma unroll
    for (int j = 0; j < 20; ++j) acc[j] = 0.0f;

    for (int cl = 0; cl < 32; ++cl) {
        float w00 = Wt[(cl*4+0)*64 + co];
        float w01 = Wt[(cl*4+1)*64 + co];
        float w10 = Wt[(cl*4+2)*64 + co];
        float w11 = Wt[(cl*4+3)*64 + co];
        #pragma unroll
        for (int j = 0; j < 20; ++j) {
            int wo = j*4 + ws;
            int c0 = 2*wo;
            acc[j] += Hs[c0*32 + cl]            * w00
                    + Hs[(c0+1)*32 + cl]        * w01
                    + Hs[(WW + c0)*32 + cl]     * w10
                    + Hs[(WW + c0 + 1)*32 + cl] * w11;
        }
    }

    float bb = 4.0f * conv_b[co];
    float s1 = 0.0f, s2 = 0.0f;
    float* ybase = g_y + (((size_t)b*CO_ + co)*HOo + ho)*WOo;
    #pragma unroll
    for (int j = 0; j < 20; ++j) {
        int wo = j*4 + ws;
        float y = ftanh(acc[j] + bb);
        ybase[wo] = y;
        s1 += y;
        s2 += y*y;
    }
    s1 += __shfl_down_sync(0xffffffffu, s1, 1, 4);
    s1 += __shfl_down_sync(0xffffffffu, s1, 2, 4);
    s2 += __shfl_down_sync(0xffffffffu, s2, 1, 4);
    s2 += __shfl_down_sync(0xffffffffu, s2, 2, 4);
    if (ws == 0) {
        int pp = b*HOo + ho;
        g_ps1[pp*CO_ + co] = s1;
        g_ps2[pp*CO_ + co] = s2;
    }
}

// ---------------- kernel 3: per-channel mean/var -> scale/shift ----------------
__global__ void reduce_kernel(const float* __restrict__ gamma, const float* __restrict__ beta) {
    __shared__ float sh1[256];
    __shared__ float sh2[256];
    const int co = blockIdx.x;
    const int t  = threadIdx.x;
    float s1 = 0.0f, s2 = 0.0f;
    for (int p = t; p < BB*HOo; p += 256) {
        s1 += g_ps1[p*CO_ + co];
        s2 += g_ps2[p*CO_ + co];
    }
    sh1[t] = s1; sh2[t] = s2;
    __syncthreads();
    for (int s = 128; s > 0; s >>= 1) {
        if (t < s) { sh1[t] += sh1[t+s]; sh2[t] += sh2[t+s]; }
        __syncthreads();
    }
    if (t == 0) {
        const float N = (float)(BB*HOo*WOo);
        float mean = sh1[0] / N;
        float var  = sh2[0] / N - mean*mean;
        float sc = gamma[co] * rsqrtf(var + 1e-5f);
        g_sc[co] = sc;
        g_sh[co] = beta[co] - mean*sc;
    }
}

// ---------------- kernel 4: normalize ----------------
__global__ void norm_kernel(float* __restrict__ out) {
    int t  = blockIdx.x * blockDim.x + threadIdx.x;
    int i0 = t * 4;
    int co = (i0 / (HOo*WOo)) & 63;
    float sc = g_sc[co], sh = g_sh[co];
    float4 v = *(const float4*)(g_y + i0);
    v.x = v.x*sc + sh;
    v.y = v.y*sc + sh;
    v.z = v.z*sc + sh;
    v.w = v.w*sc + sh;
    *(float4*)(out + i0) = v;
}

// ---------------- launcher ----------------
extern "C" void kernel_launch(void* const* d_in, const int* in_sizes, int n_in,
                              void* d_out, int out_size) {
    (void)in_sizes; (void)n_in; (void)out_size;
    const float* x      = (const float*)d_in[0];
    const float* Wx     = (const float*)d_in[1];
    const float* Ul     = (const float*)d_in[2];
    const float* Ut     = (const float*)d_in[3];
    const float* bias   = (const float*)d_in[4];
    const float* conv_w = (const float*)d_in[5];
    const float* conv_b = (const float*)d_in[6];
    const float* gamma  = (const float*)d_in[7];
    const float* beta   = (const float*)d_in[8];
    float* out = (float*)d_out;

    cudaFuncSetAttribute(mdlstm_kernel, cudaFuncAttributeMaxDynamicSharedMemorySize, SM_TOT*4);
    cudaFuncSetAttribute(conv_kernel,   cudaFuncAttributeMaxDynamicSharedMemorySize, (10240+8192)*4);

    prep_kernel<<<7680, 256>>>(x);
    mdlstm_kernel<<<4*NPAIR, 512, SM_TOT*4>>>(Wx, Ul, Ut, bias);
    conv_kernel<<<dim3(HOo, BB), 256, (10240+8192)*4>>>(conv_w, conv_b);
    reduce_kernel<<<CO_, 256>>>(gamma, beta);
    norm_kernel<<<3840, 256>>>(out);
}

// round 8
// speedup vs baseline: 1.2765x; 1.2765x over previous
#include <cuda_runtime.h>
#include <cstdint>

// ---------------- problem constants ----------------
#define HH   48
#define WW   160
#define BB   32
#define CIn  32
#define NG   160            // 5*CL
#define CO_  64
#define HOo  24
#define WOo  80
#define CELLSZ 1024         // B*CL
#define DIRSZ  (HH*WW*CELLSZ)
#define NPAIR 24            // HH/2

// ---------------- device scratch (static: allocation-free) ----------------
__device__ float    g_xT[HH*WW*BB*CIn];      // [r][c][b][ci]
__device__ float    g_hd[4*DIRSZ];           // h per direction, scan coords
__device__ float    g_cd[4*DIRSZ];           // c per direction (odd rows used)
__device__ unsigned g_prog[4*NPAIR];         // per-(dir,pair) boundary progress
__device__ float    g_y [BB*CO_*HOo*WOo];    // pre-norm conv output
__device__ float    g_ps1[BB*HOo*CO_];
__device__ float    g_ps2[BB*HOo*CO_];
__device__ float    g_sc[CO_];
__device__ float    g_sh[CO_];

// ---------------- helpers ----------------
__device__ __forceinline__ unsigned ld_acq(const unsigned* p) {
    unsigned v;
    asm volatile("ld.acquire.gpu.global.u32 %0, [%1];" : "=r"(v) : "l"(p) : "memory");
    return v;
}
__device__ __forceinline__ void st_rel(unsigned* p, unsigned v) {
    asm volatile("st.release.gpu.global.u32 [%0], %1;" :: "l"(p), "r"(v) : "memory");
}
__device__ __forceinline__ float fsigmoid(float x) {
    float e = __expf(-x);
    return __fdividef(1.0f, 1.0f + e);
}
__device__ __forceinline__ float ftanh(float x) {
    float ax = fabsf(x);
    float e  = __expf(-2.0f * ax);          // in (0,1], never overflows
    float r  = __fdividef(1.0f - e, 1.0f + e);
    return copysignf(r, x);
}

// ---------------- kernel 0: transpose x + reset progress ----------------
__global__ void prep_kernel(const float* __restrict__ x) {
    int t = blockIdx.x * blockDim.x + threadIdx.x;   // 7680*256 threads, 1 float4 each
    if (t < 4*NPAIR) g_prog[t] = 0;
    int i0 = t * 4;
    int ci = i0 & 31;
    int b  = (i0 >> 5) & 31;
    int c  = (i0 >> 10) % WW;
    int r  = i0 / (WW * CELLSZ);
    const float* xp = x + (((size_t)(b*CIn + ci))*HH + r)*WW + c;
    float4 v;
    v.x = xp[0];
    v.y = xp[(size_t)HH*WW];
    v.z = xp[2*(size_t)HH*WW];
    v.w = xp[3*(size_t)HH*WW];
    *(float4*)(g_xT + i0) = v;
}

// noop kernels: shift ncu's "-s 5 -c 1" capture window onto mdlstm_kernel
__global__ void noop_kernel() {}

// ---------------- kernel 1: 4-dir MDLSTM, paired rows, 96 CTAs x 256 thr ----------------
// smem floats:
//   Ws[96*160]=15360 | Bs[160] | At[96*68]=6528 (A transposed: [k][row])
//   Zs[64*164]=10496 | Zs2[64*164]=10496 | Cl[2048] | Ct0[1024] | Ct1[1024]
#define ATP 68
#define ZP  164
#define SM_WS  0
#define SM_BS  15360
#define SM_AT  15520
#define SM_ZS  22048
#define SM_Z2  32544
#define SM_CL  43040
#define SM_CT0 45088
#define SM_CT1 46112
#define SM_TOT 47136     // floats -> 188,544 bytes

__launch_bounds__(256, 1)
__global__ void mdlstm_kernel(const float* __restrict__ Wx, const float* __restrict__ Ul,
                              const float* __restrict__ Ut, const float* __restrict__ bias) {
    extern __shared__ float sm[];
    float* Ws  = sm + SM_WS;    // [96][160]: k 0..31 Wx, 32..63 Ul, 64..95 Ut
    float* Bs  = sm + SM_BS;
    float* At  = sm + SM_AT;    // [96][68]: k-major; cols 0..31 cell0 rows, 32..63 cell1 rows
    float* Zs  = sm + SM_ZS;    // [64][164] kh=0 partial (incl bias)
    float* Zs2 = sm + SM_Z2;    // [64][164] kh=1 partial
    float* Cl  = sm + SM_CL;    // c_left [64*32]
    float* Ct0 = sm + SM_CT0;   // c_top for cell0 (external)
    float* Ct1 = sm + SM_CT1;   // c_top for cell1 (= c(r0, prev col))

    const int tid = threadIdx.x;
    const int d   = blockIdx.x / NPAIR;
    const int p   = blockIdx.x % NPAIR;
    const bool flipH = (d >= 2);
    const bool flipW = (d & 1);
    const int r0  = 2*p;
    const int r1  = 2*p + 1;
    const int r0o = flipH ? (HH-1-r0) : r0;
    const int r1o = flipH ? (HH-1-r1) : r1;

    for (int i = tid; i < 32*NG; i += 256) {
        Ws[i]         = Wx[d*32*NG + i];
        Ws[32*NG + i] = Ul[d*32*NG + i];
        Ws[64*NG + i] = Ut[d*32*NG + i];
    }
    if (tid < NG) Bs[tid] = bias[d*NG + tid];
    for (int i = tid; i < 96*ATP; i += 256) At[i] = 0.0f;
    for (int i = tid; i < 2048; i += 256) {
        Cl[i] = 0.0f;
        if (i < 1024) { Ct0[i] = 0.0f; Ct1[i] = 0.0f; }
    }
    __syncthreads();

    // GEMM mapping: tid = kh*128 + rg*16 + cg ; thread = 8 rows x 10 cols, half of k
    const int kh = tid >> 7;
    const int rg = (tid >> 4) & 7;
    const int cg = tid & 15;
    // gates mapping
    const int gcl = tid & 31;
    const int gb0 = (tid >> 5) * 8;      // 8 rows per thread
    // staging mapping
    const int sb  = tid >> 3;            // batch row 0..31
    const int sc0 = (tid & 7) * 4;       // channel base

    unsigned* myflag = &g_prog[d*NPAIR + p];
    const unsigned* upflag = (p > 0) ? &g_prog[d*NPAIR + p - 1] : 0;

    // bias slice in registers (only kh=0 uses it)
    unsigned long long breg[5];
    #pragma unroll
    for (int j = 0; j < 5; ++j)
        breg[j] = *(const unsigned long long*)(Bs + cg*10 + 2*j);

    const float* atb = At + (kh*48)*ATP + rg*8;
    const float* wb  = Ws + (kh*48)*NG  + cg*10;
    float* Zmy = (kh == 0) ? Zs : Zs2;

    for (int t = 0; t <= WW; ++t) {
        // ---- staging: x LDGs first (latency hides under the spin) ----
        float4 xv0, xv1;
        if (t < WW) {
            int c = flipW ? (WW-1-t) : t;
            xv0 = *(const float4*)(g_xT + ((size_t)(r0o*WW + c))*CELLSZ + tid*4);
        }
        if (t >= 1) {
            int c1 = t - 1;
            int c  = flipW ? (WW-1-c1) : c1;
            xv1 = *(const float4*)(g_xT + ((size_t)(r1o*WW + c))*CELLSZ + tid*4);
        }
        if (t < WW && p > 0) {
            if (tid == 0) { while ((int)ld_acq(upflag) < t + 1) { } }
            __syncthreads();
            size_t hb = (((size_t)(d*HH + r0 - 1))*WW + t)*CELLSZ + tid*4;
            float4 hv = *(const float4*)(g_hd + hb);
            float4 cv = *(const float4*)(g_cd + hb);
            // h_top for cell0: At[64+cl][b]
            At[(64 + sc0 + 0)*ATP + sb] = hv.x;
            At[(64 + sc0 + 1)*ATP + sb] = hv.y;
            At[(64 + sc0 + 2)*ATP + sb] = hv.z;
            At[(64 + sc0 + 3)*ATP + sb] = hv.w;
            *(float4*)(Ct0 + tid*4) = cv;
        }
        if (t < WW) {
            At[(sc0 + 0)*ATP + sb] = xv0.x;
            At[(sc0 + 1)*ATP + sb] = xv0.y;
            At[(sc0 + 2)*ATP + sb] = xv0.z;
            At[(sc0 + 3)*ATP + sb] = xv0.w;
        }
        if (t >= 1) {
            At[(sc0 + 0)*ATP + 32 + sb] = xv1.x;
            At[(sc0 + 1)*ATP + 32 + sb] = xv1.y;
            At[(sc0 + 2)*ATP + 32 + sb] = xv1.z;
            At[(sc0 + 3)*ATP + 32 + sb] = xv1.w;
        }
        __syncthreads();

        // ---- GEMM: thread computes 8 rows x 10 cols over its k-half ----
        {
            unsigned long long acc[8][5];
            #pragma unroll
            for (int r = 0; r < 8; ++r)
                #pragma unroll
                for (int j = 0; j < 5; ++j)
                    acc[r][j] = (kh == 0) ? breg[j] : 0ull;

            #pragma unroll 2
            for (int k = 0; k < 48; ++k) {
                float4 alo = *(const float4*)(atb + k*ATP);
                float4 ahi = *(const float4*)(atb + k*ATP + 4);
                unsigned long long wv[5];
                #pragma unroll
                for (int j = 0; j < 5; ++j)
                    wv[j] = *(const unsigned long long*)(wb + k*NG + 2*j);
                float av[8] = {alo.x, alo.y, alo.z, alo.w, ahi.x, ahi.y, ahi.z, ahi.w};
                #pragma unroll
                for (int r = 0; r < 8; ++r) {
                    unsigned long long aa;
                    asm("mov.b64 %0, {%1, %1};" : "=l"(aa) : "f"(av[r]));
                    #pragma unroll
                    for (int j = 0; j < 5; ++j)
                        asm("fma.rn.f32x2 %0, %1, %2, %0;" : "+l"(acc[r][j]) : "l"(wv[j]), "l"(aa));
                }
            }
            float* zb = Zmy + (rg*8)*ZP + cg*10;
            #pragma unroll
            for (int r = 0; r < 8; ++r)
                #pragma unroll
                for (int j = 0; j < 5; ++j)
                    *(unsigned long long*)(zb + r*ZP + 2*j) = acc[r][j];
        }
        __syncthreads();

        // ---- gates for both cells (8 rows per thread) ----
        {
            const bool act0 = (t < WW);
            const bool act1 = (t >= 1);
            size_t base0 = (((size_t)(d*HH + r0))*WW + t)*CELLSZ;
            size_t base1 = (((size_t)(d*HH + r1))*WW + (t-1))*CELLSZ;
            #pragma unroll
            for (int j = 0; j < 8; ++j) {
                int gr = gb0 + j;
                const float* z1 = Zs  + gr*ZP + gcl;
                const float* z2 = Zs2 + gr*ZP + gcl;
                float zi  = z1[0]   + z2[0];
                float zfl = z1[32]  + z2[32];
                float zft = z1[64]  + z2[64];
                float zo  = z1[96]  + z2[96];
                float zg  = z1[128] + z2[128];
                int b = gr & 31;
                float cle = Cl[gr*32 + gcl];
                float cto = (gr < 32) ? Ct0[b*32 + gcl] : Ct1[b*32 + gcl];
                float cs = fsigmoid(zfl)*cle + fsigmoid(zft)*cto
                         + fsigmoid(zi)*ftanh(zg);
                float h  = fsigmoid(zo)*ftanh(cs);
                if (gr < 32) {
                    if (act0) {
                        Cl[gr*32 + gcl]           = cs;
                        At[(32+gcl)*ATP + gr]     = h;    // h_left(r0)
                        Ct1[b*32 + gcl]           = cs;   // c_top for cell1 next step
                        At[(64+gcl)*ATP + 32 + b] = h;    // h_top for cell1 next step
                        g_hd[base0 + b*32 + gcl]  = h;
                    }
                } else {
                    if (act1) {
                        Cl[gr*32 + gcl]           = cs;
                        At[(32+gcl)*ATP + gr]     = h;    // h_left(r1)
                        g_hd[base1 + b*32 + gcl]  = h;    // boundary row
                        g_cd[base1 + b*32 + gcl]  = cs;
                    }
                }
            }
        }
        __syncthreads();
        if (tid == 0 && t >= 1) {
            __threadfence();
            st_rel(myflag, (unsigned)t);
        }
    }
}

// ---------------- kernel 2: 4-dir sum + 2x2/2 conv + tanh + partial stats ----------------
__launch_bounds__(256, 2)
__global__ void conv_kernel(const float* __restrict__ conv_w, const float* __restrict__ conv_b) {
    extern __shared__ float sm2[];
    float* Hs = sm2;            // [rr][c][cl]  2*160*32
    float* Wt = sm2 + 10240;    // [cl*4+kh*2+kw][co] 128*64
    const int ho  = blockIdx.x;
    const int b   = blockIdx.y;
    const int tid = threadIdx.x;

    for (int i = tid; i < 128*64; i += 256) {
        int co = i & 63, q = i >> 6;
        Wt[i] = conv_w[co*128 + q];
    }
    for (int idx = tid; idx < 2*WW*32; idx += 256) {
        int cl = idx & 31;
        int c  = (idx >> 5) % WW;
        int rr = idx / (WW*32);
        int rg = 2*ho + rr;
        float v = 0.0f;
        #pragma unroll
        for (int d = 0; d < 4; ++d) {
            int Rd = (d >= 2) ? (HH-1-rg) : rg;
            int Cd = (d & 1)  ? (WW-1-c)  : c;
            v += g_hd[(((size_t)(d*HH + Rd))*WW + Cd)*CELLSZ + b*32 + cl];
        }
        Hs[idx] = v;
    }
    __syncthreads();

    const int co = tid >> 2;
    const int ws = tid & 3;
    float acc[20];
    #pragma unroll
    for (int j = 0; j < 20; ++j) acc[j] = 0.0f;

    for (int cl = 0; cl < 32; ++cl) {
        float w00 = Wt[(cl*4+0)*64 + co];
        float w01 = Wt[(cl*4+1)*64 + co];
        float w10 = Wt[(cl*4+2)*64 + co];
        float w11 = Wt[(cl*4+3)*64 + co];
        #pragma unroll
        for (int j = 0; j < 20; ++j) {
            int wo = j*4 + ws;
            int c0 = 2*wo;
            acc[j] += Hs[c0*32 + cl]            * w00
                    + Hs[(c0+1)*32 + cl]        * w01
                    + Hs[(WW + c0)*32 + cl]     * w10
                    + Hs[(WW + c0 + 1)*32 + cl] * w11;
        }
    }

    float bb = 4.0f * conv_b[co];
    float s1 = 0.0f, s2 = 0.0f;
    float* ybase = g_y + (((size_t)b*CO_ + co)*HOo + ho)*WOo;
    #pragma unroll
    for (int j = 0; j < 20; ++j) {
        int wo = j*4 + ws;
        float y = ftanh(acc[j] + bb);
        ybase[wo] = y;
        s1 += y;
        s2 += y*y;
    }
    s1 += __shfl_down_sync(0xffffffffu, s1, 1, 4);
    s1 += __shfl_down_sync(0xffffffffu, s1, 2, 4);
    s2 += __shfl_down_sync(0xffffffffu, s2, 1, 4);
    s2 += __shfl_down_sync(0xffffffffu, s2, 2, 4);
    if (ws == 0) {
        int pp = b*HOo + ho;
        g_ps1[pp*CO_ + co] = s1;
        g_ps2[pp*CO_ + co] = s2;
    }
}

// ---------------- kernel 3: per-channel mean/var -> scale/shift ----------------
__global__ void reduce_kernel(const float* __restrict__ gamma, const float* __restrict__ beta) {
    __shared__ float sh1[256];
    __shared__ float sh2[256];
    const int co = blockIdx.x;
    const int t  = threadIdx.x;
    float s1 = 0.0f, s2 = 0.0f;
    for (int p = t; p < BB*HOo; p += 256) {
        s1 += g_ps1[p*CO_ + co];
        s2 += g_ps2[p*CO_ + co];
    }
    sh1[t] = s1; sh2[t] = s2;
    __syncthreads();
    for (int s = 128; s > 0; s >>= 1) {
        if (t < s) { sh1[t] += sh1[t+s]; sh2[t] += sh2[t+s]; }
        __syncthreads();
    }
    if (t == 0) {
        const float N = (float)(BB*HOo*WOo);
        float mean = sh1[0] / N;
        float var  = sh2[0] / N - mean*mean;
        float sc = gamma[co] * rsqrtf(var + 1e-5f);
        g_sc[co] = sc;
        g_sh[co] = beta[co] - mean*sc;
    }
}

// ---------------- kernel 4: normalize ----------------
__global__ void norm_kernel(float* __restrict__ out) {
    int t  = blockIdx.x * blockDim.x + threadIdx.x;
    int i0 = t * 4;
    int co = (i0 / (HOo*WOo)) & 63;
    float sc = g_sc[co], sh = g_sh[co];
    float4 v = *(const float4*)(g_y + i0);
    v.x = v.x*sc + sh;
    v.y = v.y*sc + sh;
    v.z = v.z*sc + sh;
    v.w = v.w*sc + sh;
    *(float4*)(out + i0) = v;
}

// ---------------- launcher ----------------
extern "C" void kernel_launch(void* const* d_in, const int* in_sizes, int n_in,
                              void* d_out, int out_size) {
    (void)in_sizes; (void)n_in; (void)out_size;
    const float* x      = (const float*)d_in[0];
    const float* Wx     = (const float*)d_in[1];
    const float* Ul     = (const float*)d_in[2];
    const float* Ut     = (const float*)d_in[3];
    const float* bias   = (const float*)d_in[4];
    const float* conv_w = (const float*)d_in[5];
    const float* conv_b = (const float*)d_in[6];
    const float* gamma  = (const float*)d_in[7];
    const float* beta   = (const float*)d_in[8];
    float* out = (float*)d_out;

    cudaFuncSetAttribute(mdlstm_kernel, cudaFuncAttributeMaxDynamicSharedMemorySize, SM_TOT*4);
    cudaFuncSetAttribute(conv_kernel,   cudaFuncAttributeMaxDynamicSharedMemorySize, (10240+8192)*4);

    prep_kernel<<<7680, 256>>>(x);
    // 4 no-ops so ncu (-s 5 -c 1) captures mdlstm_kernel as the 6th launch
    noop_kernel<<<1, 32>>>();
    noop_kernel<<<1, 32>>>();
    noop_kernel<<<1, 32>>>();
    noop_kernel<<<1, 32>>>();
    mdlstm_kernel<<<4*NPAIR, 256, SM_TOT*4>>>(Wx, Ul, Ut, bias);
    conv_kernel<<<dim3(HOo, BB), 256, (10240+8192)*4>>>(conv_w, conv_b);
    reduce_kernel<<<CO_, 256>>>(gamma, beta);
    norm_kernel<<<3840, 256>>>(out);
}